// round 13
// baseline (speedup 1.0000x reference)
#include <cuda_runtime.h>
#include <math.h>

#define KB 10
#define VV 50257
#define EE 128
#define H1D 128
#define H2D 64
#define QQ 64
#define TENC 2048
#define MAXLEN 30
#define SOSTOK 1
#define EOSTOK 2
#define GRID 148
#define NTHR 512
#define RPB 340            // 148*340 = 50320 >= 50257
#define LGW 513            // padded logits row width (bank-conflict-free)
#define NCHUNK 8
#define CHUNK 256
#define NUNITS (KB*NCHUNK) // 80
#define SEQW (MAXLEN + 1)  // 31
#define TPB 12
#define NCAND (GRID*KB*TPB)

// ---------------- persistent device state ----------------
__device__ float g_h1[KB*H1D], g_c1[KB*H1D], g_ctx[KB*QQ];
__device__ __align__(16) float g_h2[KB*H2D];
__device__ float g_c2[KB*H2D];
__device__ float g_h1n[KB*H1D], g_c1n[KB*H1D], g_c2n[KB*H2D], g_ctxn[KB*QQ];
__device__ __align__(16) float g_h2n[KB*H2D];
__device__ float g_scores[KB];
__device__ int   g_prev[KB], g_fin[KB], g_seqs[KB*SEQW];
__device__ float g_attM[KB*NCHUNK], g_attA[KB*NCHUNK], g_attB[KB*NCHUNK];
__device__ float g_attC[KB*NCHUNK*QQ];
__device__ double g_sump[GRID*KB];
__device__ float g_cand_val[NCAND];
__device__ int   g_cand_idx[NCAND];
__device__ unsigned g_count = 0;
__device__ unsigned g_epoch = 0;

__device__ __forceinline__ unsigned ordkey(float f){
  unsigned u = __float_as_uint(f);
  return (u & 0x80000000u) ? ~u : (u | 0x80000000u);
}
__device__ __forceinline__ float unordkey(unsigned k){
  unsigned u = (k & 0x80000000u) ? (k & 0x7FFFFFFFu) : ~k;
  return __uint_as_float(u);
}
__device__ __forceinline__ void ffma2(unsigned long long& d, unsigned long long a, unsigned long long b){
  asm("fma.rn.f32x2 %0, %1, %2, %0;" : "+l"(d) : "l"(a), "l"(b));
}
// compensated fp32 FMA accumulate: true value ~= s - c
__device__ __forceinline__ void kfma(float& s, float& c, float a, float b){
  float p  = __fmul_rn(a, b);
  float e  = __fmaf_rn(a, b, -p);
  float y  = p - c;
  float t2 = s + y;
  c = (t2 - s) - y;
  s = t2;
  c -= e;
}

// ---------------- grid barrier with backoff ----------------
__device__ __forceinline__ void gridbar(unsigned& ep){
  __syncthreads();
  if (threadIdx.x==0){
    __threadfence();
    unsigned prev = atomicAdd(&g_count, 1u);
    if (prev == GRID-1u){
      g_count = 0u;
      __threadfence();
      atomicAdd(&g_epoch, 1u);
    } else {
      volatile unsigned* e = &g_epoch;
      while ((int)(*e - ep) < 1) __nanosleep(32);
    }
    __threadfence();
  }
  __syncthreads();
  ep++;
}

// ---------------- shared-memory phase overlays ----------------
struct SM_L {            // fused LSTM1+LSTM2 per-beam (~10.5KB)
  float sx[192];
  float sh1[H1D];
  float sh1n[H1D];
  float sh2[H2D];
  double sgd[512];
  double snl[512];
};
struct SM_AT {           // attention partials (~5.7KB)
  float h2s[H2D]; float qp[4][QQ]; float qs[QQ]; float ws[CHUNK]; float se[CHUNK];
  float redm[8]; float redab[8][2]; float cs[8][QQ];
};
struct SM_LO {           // logits (~21.7KB)
  float lg[KB*LGW];
  float wred[16][KB];
  float sM[KB]; float scf[KB][NCHUNK];
  double sA[KB]; double sB[KB];
};
struct SM_SE {           // select (~24.3KB)
  double sp[256]; unsigned long long skeys[256*10]; unsigned long long wmax[16];
  unsigned long long swin; unsigned long long topk[KB];
  float slse[KB]; float sscore[KB]; float sval[KB];
  int sfin[KB]; int spb[KB]; int stok[KB]; int sseq[KB*SEQW];
};
#define SMRAW_BYTES 25600

__global__ void __launch_bounds__(NTHR) mega_kernel(
  const float* __restrict__ enc_key, const float* __restrict__ enc_val,
  const float* __restrict__ mask,    const float* __restrict__ emb,
  const float* __restrict__ Wih1, const float* __restrict__ Whh1,
  const float* __restrict__ bih1, const float* __restrict__ bhh1,
  const float* __restrict__ Wih2, const float* __restrict__ Whh2,
  const float* __restrict__ bih2, const float* __restrict__ bhh2,
  const float* __restrict__ Wq, const float* __restrict__ bq,
  const float* __restrict__ Wc, const float* __restrict__ bc,
  float* __restrict__ out)
{
  __shared__ __align__(16) char smraw[SMRAW_BYTES];
  __shared__ unsigned s_ep0;
  int t = threadIdx.x, bid = blockIdx.x;
  int lane = t & 31, wid = t >> 5;

  static_assert(sizeof(SM_L)  <= SMRAW_BYTES, "SM_L overflow");
  static_assert(sizeof(SM_AT) <= SMRAW_BYTES, "SM_AT overflow");
  static_assert(sizeof(SM_LO) <= SMRAW_BYTES, "SM_LO overflow");
  static_assert(sizeof(SM_SE) <= SMRAW_BYTES, "SM_SE overflow");

  if (t==0){
    volatile unsigned* e = &g_epoch;
    s_ep0 = *e;
  }
  __syncthreads();
  unsigned ep = s_ep0;

  if (bid==0){
    for (int i=t;i<KB*H1D;i+=NTHR){ g_h1[i]=0.f; g_c1[i]=0.f; }
    for (int i=t;i<KB*H2D;i+=NTHR){ g_h2[i]=0.f; g_c2[i]=0.f; }
    for (int i=t;i<KB*QQ;i+=NTHR)  g_ctx[i]=0.f;
    for (int i=t;i<KB*SEQW;i+=NTHR) g_seqs[i]=SOSTOK;
    if (t<KB){ g_scores[t]=0.f; g_prev[t]=SOSTOK; g_fin[t]=0; }
  }
  gridbar(ep);

  for (int step=0; step<MAXLEN; step++){

    // ============ Phase L: fused LSTM1+LSTM2 per beam (blocks 0..9) ============
    if (bid < KB){
      SM_L* sl = (SM_L*)smraw;
      int b = bid;
      for (int i=t;i<192;i+=NTHR)
        sl->sx[i] = (i<EE) ? emb[(size_t)g_prev[b]*EE + i] : g_ctx[b*QQ + (i-EE)];
      for (int i=t;i<H1D;i+=NTHR) sl->sh1[i] = g_h1[b*H1D+i];
      for (int i=t;i<H2D;i+=NTHR) sl->sh2[i] = g_h2[b*H2D+i];
      __syncthreads();

      // LSTM1: 512 gate-dots, warp-per-dot (bit-identical lane pattern)
      for (int d = wid; d < 512; d += 16){
        const float* wi = Wih1 + (size_t)d*192;
        const float* wh = Whh1 + (size_t)d*H1D;
        float s=0.f, c=0.f;
        #pragma unroll 2
        for (int j=lane;j<192;j+=32) kfma(s, c, wi[j], sl->sx[j]);
        #pragma unroll 2
        for (int j=lane;j<H1D;j+=32) kfma(s, c, wh[j], sl->sh1[j]);
        for (int o=16;o>0;o>>=1){
          s += __shfl_down_sync(0xffffffffu, s, o);
          c += __shfl_down_sync(0xffffffffu, c, o);
        }
        if (lane==0) sl->sgd[d] = ((double)s - (double)c) + ((double)bih1[d] + (double)bhh1[d]);
      }
      __syncthreads();
      if (t < 512){
        int g = t>>7;
        double v = sl->sgd[t];
        sl->snl[t] = (g==2) ? tanh(v) : 1.0/(1.0+exp(-v));
      }
      __syncthreads();
      if (t < H1D){
        int n = t;
        double cd = sl->snl[128+n]*(double)g_c1[b*H1D+n] + sl->snl[n]*sl->snl[256+n];
        float cf = (float)cd;
        g_c1n[b*H1D+n] = cf;
        float hf = (float)(sl->snl[384+n]*tanh((double)cf));
        sl->sh1n[n] = hf;
        g_h1n[b*H1D+n] = hf;
      }
      __syncthreads();

      // LSTM2: 256 gate-dots
      for (int d = wid; d < 256; d += 16){
        const float* wi = Wih2 + (size_t)d*H1D;
        const float* wh = Whh2 + (size_t)d*H2D;
        float s=0.f, c=0.f;
        #pragma unroll 2
        for (int j=lane;j<H1D;j+=32) kfma(s, c, wi[j], sl->sh1n[j]);
        for (int j=lane;j<H2D;j+=32) kfma(s, c, wh[j], sl->sh2[j]);
        for (int o=16;o>0;o>>=1){
          s += __shfl_down_sync(0xffffffffu, s, o);
          c += __shfl_down_sync(0xffffffffu, c, o);
        }
        if (lane==0) sl->sgd[d] = ((double)s - (double)c) + ((double)bih2[d] + (double)bhh2[d]);
      }
      __syncthreads();
      if (t < 256){
        int g = t>>6;
        double v = sl->sgd[t];
        sl->snl[t] = (g==2) ? tanh(v) : 1.0/(1.0+exp(-v));
      }
      __syncthreads();
      if (t < H2D){
        int n = t;
        double cd = sl->snl[64+n]*(double)g_c2[b*H2D+n] + sl->snl[n]*sl->snl[128+n];
        float cf = (float)cd;
        g_c2n[b*H2D+n] = cf;
        g_h2n[b*H2D+n] = (float)(sl->snl[192+n]*tanh((double)cf));
      }
    }
    gridbar(ep);

    // ============ attention: 80 units (beam, 256-token chunk) ============
    if (bid < NUNITS){
      SM_AT* sa = (SM_AT*)smraw;
      int beam = bid>>3, ch = bid&7;
      if (t<H2D) sa->h2s[t] = g_h2n[beam*H2D+t];
      __syncthreads();
      if (t < 256){
        int qi = t&63, part = t>>6;
        const float* w = Wq + qi*H2D + part*16;
        float s=0.f, c=0.f;
        #pragma unroll
        for (int j=0;j<16;j++) kfma(s, c, w[j], sa->h2s[part*16+j]);
        sa->qp[part][qi] = s - c;
      }
      __syncthreads();
      if (t<QQ) sa->qs[t] = bq[t] + ((sa->qp[0][t]+sa->qp[1][t])+(sa->qp[2][t]+sa->qp[3][t]));
      __syncthreads();
      // energies: 16-lane group per token, coalesced key reads
      {
        int half = lane>>4, l16 = lane&15;
        float4 qv = ((const float4*)sa->qs)[l16];
        #pragma unroll
        for (int it=0; it<8; it++){
          int tl = it*32 + wid*2 + half;          // 0..255
          int tok = ch*CHUNK + tl;
          float4 kv = ((const float4*)(enc_key + (size_t)tok*QQ))[l16];
          float s=0.f, c=0.f;
          kfma(s,c,qv.x,kv.x); kfma(s,c,qv.y,kv.y);
          kfma(s,c,qv.z,kv.z); kfma(s,c,qv.w,kv.w);
          float p = s - c;
          for (int o=8;o>0;o>>=1) p += __shfl_down_sync(0xffffffffu, p, o);
          if (l16==0) sa->se[tl] = p;
        }
      }
      __syncthreads();
      float e = -1e30f;
      if (t < 256) e = sa->se[t];
      float m = e;
      for (int o=16;o>0;o>>=1) m = fmaxf(m, __shfl_down_sync(0xffffffffu, m, o));
      if (lane==0 && wid<8) sa->redm[wid]=m;
      __syncthreads();
      float M = sa->redm[0];
      #pragma unroll
      for (int q=1;q<8;q++) M = fmaxf(M, sa->redm[q]);
      float wexp=0.f, wmask=0.f;
      if (t < 256){
        int tok = ch*CHUNK + t;
        wexp = expf(e-M);
        wmask = wexp*mask[tok];
        sa->ws[t] = wmask;
      }
      float a=wexp, b2=wmask;
      for (int o=16;o>0;o>>=1){
        a  += __shfl_down_sync(0xffffffffu, a, o);
        b2 += __shfl_down_sync(0xffffffffu, b2, o);
      }
      if (lane==0 && wid<8){ sa->redab[wid][0]=a; sa->redab[wid][1]=b2; }
      __syncthreads();
      {
        int v = t&63, grp = t>>6;      // 8 groups x 32 tokens
        const float* vb = enc_val + (size_t)(ch*CHUNK + grp*32)*QQ + v;
        float s0=0,c0=0,s1=0,c1=0;
        #pragma unroll 4
        for (int tl=0; tl<32; tl+=2){
          kfma(s0,c0, sa->ws[grp*32+tl],   vb[(size_t)tl*QQ]);
          kfma(s1,c1, sa->ws[grp*32+tl+1], vb[(size_t)(tl+1)*QQ]);
        }
        sa->cs[grp][v] = (s0-c0)+(s1-c1);
      }
      __syncthreads();
      if (t<QQ){
        float cc = ((sa->cs[0][t]+sa->cs[1][t])+(sa->cs[2][t]+sa->cs[3][t]))
                 + ((sa->cs[4][t]+sa->cs[5][t])+(sa->cs[6][t]+sa->cs[7][t]));
        g_attC[(beam*NCHUNK+ch)*QQ + t] = cc;
      }
      if (t==0){
        g_attM[beam*NCHUNK+ch]=M;
        g_attA[beam*NCHUNK+ch]=((sa->redab[0][0]+sa->redab[1][0])+(sa->redab[2][0]+sa->redab[3][0]))
                              +((sa->redab[4][0]+sa->redab[5][0])+(sa->redab[6][0]+sa->redab[7][0]));
        g_attB[beam*NCHUNK+ch]=((sa->redab[0][1]+sa->redab[1][1])+(sa->redab[2][1]+sa->redab[3][1]))
                              +((sa->redab[4][1]+sa->redab[5][1])+(sa->redab[6][1]+sa->redab[7][1]));
      }
    }
    gridbar(ep);

    // ============ logits: all 148 blocks, x built directly in registers ============
    {
      SM_LO* so = (SM_LO*)smraw;
      if (t<KB){
        float M=-1e30f;
        #pragma unroll
        for (int c=0;c<NCHUNK;c++) M = fmaxf(M, g_attM[t*NCHUNK+c]);
        so->sM[t]=M;
      }
      __syncthreads();
      if (t<KB*NCHUNK){
        int b=t/NCHUNK;
        so->scf[b][t%NCHUNK] = expf(g_attM[t]-so->sM[b]);
      }
      __syncthreads();
      if (t<KB){
        double A=0.0, B=0.0;
        #pragma unroll
        for (int c=0;c<NCHUNK;c++){
          A += (double)g_attA[t*NCHUNK+c]*(double)so->scf[t][c];
          B += (double)g_attB[t*NCHUNK+c]*(double)so->scf[t][c];
        }
        so->sA[t]=A; so->sB[t]=B;
      }
      __syncthreads();
      // each lane builds its own 16B x-chunk per beam
      ulonglong2 xv[KB];
      if (lane < 16){
        #pragma unroll
        for (int b=0;b<KB;b++){
          float4 h4 = ((const float4*)g_h2n)[b*16 + lane];
          ulonglong2 u;
          u.x = ((unsigned long long)__float_as_uint(h4.y)<<32) | __float_as_uint(h4.x);
          u.y = ((unsigned long long)__float_as_uint(h4.w)<<32) | __float_as_uint(h4.z);
          xv[b] = u;
        }
      } else {
        int v0 = (lane-16)*4;
        #pragma unroll
        for (int b=0;b<KB;b++){
          float xc[4];
          double A = so->sA[b], B = so->sB[b];
          double denom = fmax(B/A, 2e-30);
          #pragma unroll
          for (int k=0;k<4;k++){
            int v = v0 + k;
            float s=0.f, c=0.f;
            #pragma unroll
            for (int cc=0;cc<NCHUNK;cc++) kfma(s, c, g_attC[(b*NCHUNK+cc)*QQ+v], so->scf[b][cc]);
            double Cd = (double)s - (double)c;
            xc[k] = (float)((Cd/A) / denom);
          }
          if (bid==0 && wid==0){
            #pragma unroll
            for (int k=0;k<4;k++) g_ctxn[b*QQ + v0 + k] = xc[k];
          }
          ulonglong2 u;
          u.x = ((unsigned long long)__float_as_uint(xc[1])<<32) | __float_as_uint(xc[0]);
          u.y = ((unsigned long long)__float_as_uint(xc[3])<<32) | __float_as_uint(xc[2]);
          xv[b] = u;
        }
      }
      // warp-per-row GEMV from registers
      for (int rr = wid; rr < RPB; rr += 16){
        int v = bid*RPB + rr;
        bool ok = v < VV;
        ulonglong2 wv = ((const ulonglong2*)(Wc + (size_t)(ok?v:0)*128))[lane];
        float p[KB];
        #pragma unroll
        for (int b=0;b<KB;b++){
          unsigned long long acc=0ull;
          ffma2(acc, wv.x, xv[b].x);
          ffma2(acc, wv.y, xv[b].y);
          p[b] = __uint_as_float((unsigned)(acc & 0xffffffffu))
               + __uint_as_float((unsigned)(acc >> 32));
        }
        #pragma unroll
        for (int b=0;b<KB;b++)
          for (int o=16;o>0;o>>=1) p[b] += __shfl_xor_sync(0xffffffffu, p[b], o);
        float pm = p[0];
        #pragma unroll
        for (int b=1;b<KB;b++) pm = (lane==b) ? p[b] : pm;
        if (lane < KB)
          so->lg[lane*LGW + rr] = ok ? pm + bc[v] : -1e30f;
      }
      __syncthreads();
      // all-lane exp + per-beam sumexp
      {
        float exb[KB];
        #pragma unroll
        for (int b=0;b<KB;b++)
          exb[b] = (t < RPB) ? expf(so->lg[b*LGW + t]) : 0.f;
        #pragma unroll
        for (int b=0;b<KB;b++){
          float s = exb[b];
          for (int o=16;o>0;o>>=1) s += __shfl_down_sync(0xffffffffu, s, o);
          if (lane==0) so->wred[wid][b] = s;
        }
      }
      __syncthreads();
      if (t<KB){
        double s=0.0;
        for (int w=0;w<16;w++) s += (double)so->wred[w][t];
        g_sump[bid*KB+t] = s;
      }
      // per-(beam,block) exact top-12, warp per beam
      if (wid < KB){
        int bm = wid;
        for (int j=0;j<TPB;j++){
          unsigned long long best=0ull;
          for (int r2=lane; r2<RPB; r2+=32){
            unsigned long long k = ((unsigned long long)ordkey(so->lg[bm*LGW + r2])<<32) | (unsigned)(~(unsigned)r2);
            if (k>best) best=k;
          }
          for (int o=16;o>0;o>>=1){
            unsigned long long ok = __shfl_down_sync(0xffffffffu, best, o);
            if (ok>best) best=ok;
          }
          best = __shfl_sync(0xffffffffu, best, 0);
          int rs = (int)(~(unsigned)(best & 0xffffffffu));
          if (lane==0){
            g_cand_val[(bid*KB+bm)*TPB+j] = so->lg[bm*LGW + rs];
            g_cand_idx[(bid*KB+bm)*TPB+j] = bid*RPB + rs;
            so->lg[bm*LGW + rs] = -1e30f;
          }
          __syncwarp();
        }
      }
    }
    gridbar(ep);

    // ============ select: block 0 ============
    if (bid==0){
      SM_SE* se = (SM_SE*)smraw;
      {
        double s=0.0;
        if (t < 250){
          int b = t/25, part = t%25;
          for (int b2=part; b2<GRID; b2+=25) s += g_sump[b2*KB+b];
        }
        if (t < 256) se->sp[t]=s;
      }
      __syncthreads();
      if (t<KB){
        double s=0.0;
        for (int q=0;q<25;q++) s += se->sp[t*25+q];
        se->slse[t] = (float)log(s);
        se->sscore[t] = g_scores[t];
        se->sfin[t] = g_fin[t];
      }
      __syncthreads();
      if (t < 256){
        unsigned long long list[10];
        #pragma unroll
        for (int j=0;j<10;j++) list[j]=0ull;
        for (int c=t;c<NCAND;c+=256){
          int b = (c/TPB)%KB;
          if (se->sfin[b]) continue;
          if (step==0 && b>0) continue;
          float logp = g_cand_val[c] - se->slse[b];
          float v = se->sscore[b] + logp;
          int flat = b*VV + g_cand_idx[c];
          unsigned long long k = ((unsigned long long)ordkey(v)<<32) | (unsigned)(~(unsigned)flat);
          if (k > list[9]){
            list[9]=k;
            for (int j=8;j>=0;j--){
              if (list[j] < list[j+1]){ unsigned long long tmp=list[j]; list[j]=list[j+1]; list[j+1]=tmp; }
              else break;
            }
          }
        }
        if (t<KB && se->sfin[t]){
          float v = se->sscore[t];
          int flat = t*VV + EOSTOK;
          unsigned long long k = ((unsigned long long)ordkey(v)<<32) | (unsigned)(~(unsigned)flat);
          if (k > list[9]){
            list[9]=k;
            for (int j=8;j>=0;j--){
              if (list[j] < list[j+1]){ unsigned long long tmp=list[j]; list[j]=list[j+1]; list[j+1]=tmp; }
              else break;
            }
          }
        }
        #pragma unroll
        for (int j=0;j<10;j++) se->skeys[t*10+j]=list[j];
      }
      __syncthreads();
      for (int j=0;j<10;j++){
        unsigned long long m=0ull;
        if (t < 256){
          #pragma unroll
          for (int q=0;q<10;q++){ unsigned long long k=se->skeys[t*10+q]; if (k>m) m=k; }
        }
        for (int o=16;o>0;o>>=1){
          unsigned long long ok = __shfl_down_sync(0xffffffffu, m, o);
          if (ok>m) m=ok;
        }
        if (lane==0) se->wmax[wid]=m;
        __syncthreads();
        if (t==0){
          unsigned long long w=se->wmax[0];
          for (int q=1;q<16;q++) if (se->wmax[q]>w) w=se->wmax[q];
          se->swin=w; se->topk[j]=w;
        }
        __syncthreads();
        unsigned long long win = se->swin;
        if (t < 256){
          #pragma unroll
          for (int q=0;q<10;q++) if (se->skeys[t*10+q]==win) se->skeys[t*10+q]=0ull;
        }
        __syncthreads();
      }
      if (t<KB){
        unsigned long long k = se->topk[t];
        se->sval[t] = unordkey((unsigned)(k>>32));
        int flat = (int)(~(unsigned)(k & 0xffffffffu));
        se->spb[t]  = flat / VV;
        se->stok[t] = flat % VV;
      }
      for (int i=t;i<KB*SEQW;i+=NTHR) se->sseq[i] = g_seqs[i];
      __syncthreads();
      for (int i=t;i<KB*H1D;i+=NTHR){
        int nb=i>>7, u=i&127;
        g_h1[i]=g_h1n[se->spb[nb]*H1D+u];
        g_c1[i]=g_c1n[se->spb[nb]*H1D+u];
      }
      for (int i=t;i<KB*H2D;i+=NTHR){
        int nb=i>>6, u=i&63;
        g_h2[i]=g_h2n[se->spb[nb]*H2D+u];
        g_c2[i]=g_c2n[se->spb[nb]*H2D+u];
        g_ctx[i]=g_ctxn[se->spb[nb]*QQ+u];
      }
      for (int i=t;i<KB*SEQW;i+=NTHR){
        int nb=i/SEQW, cc=i%SEQW;
        g_seqs[i] = se->sseq[se->spb[nb]*SEQW+cc];
      }
      __syncthreads();
      if (t<KB){
        g_seqs[t*SEQW + step + 1] = se->stok[t];
        g_prev[t]   = se->stok[t];
        g_scores[t] = se->sval[t];
        g_fin[t]    = se->sfin[se->spb[t]] | (se->stok[t]==EOSTOK);
      }
    }
    gridbar(ep);
  }

  // ---------- finalize: block 0 ----------
  if (bid==0){
    SM_SE* se = (SM_SE*)smraw;
    if (t<KB){
      int first=-1;
      for (int c=1;c<=MAXLEN;c++){
        if (g_seqs[t*SEQW+c]==EOSTOK){ first=c-1; break; }
      }
      float len = (first>=0) ? (float)(first+2) : (float)(MAXLEN+2);
      se->sval[t] = (float)((double)g_scores[t] / pow((double)len, 1.2));
    }
    __syncthreads();
    for (int i=t;i<KB*SEQW;i+=NTHR) out[i] = (float)g_seqs[i];
    if (t<KB){
      out[KB*SEQW + t]       = g_scores[t];
      out[KB*SEQW + KB + t]  = se->sval[t];
    }
  }
}

extern "C" void kernel_launch(void* const* d_in, const int* in_sizes, int n_in,
                              void* d_out, int out_size){
  const float* enc_key = (const float*)d_in[0];
  const float* enc_val = (const float*)d_in[1];
  const float* mask    = (const float*)d_in[2];
  const float* emb     = (const float*)d_in[3];
  const float* Wih1    = (const float*)d_in[4];
  const float* Whh1    = (const float*)d_in[5];
  const float* bih1    = (const float*)d_in[6];
  const float* bhh1    = (const float*)d_in[7];
  const float* Wih2    = (const float*)d_in[8];
  const float* Whh2    = (const float*)d_in[9];
  const float* bih2    = (const float*)d_in[10];
  const float* bhh2    = (const float*)d_in[11];
  const float* Wq      = (const float*)d_in[12];
  const float* bq      = (const float*)d_in[13];
  const float* Wc      = (const float*)d_in[14];
  const float* bc      = (const float*)d_in[15];

  mega_kernel<<<GRID,NTHR>>>(enc_key, enc_val, mask, emb,
                             Wih1, Whh1, bih1, bhh1,
                             Wih2, Whh2, bih2, bhh2,
                             Wq, bq, Wc, bc, (float*)d_out);
}

// round 14
// speedup vs baseline: 2.7615x; 2.7615x over previous
#include <cuda_runtime.h>
#include <math.h>

#define KB 10
#define VV 50257
#define EE 128
#define H1D 128
#define H2D 64
#define QQ 64
#define TENC 2048
#define MAXLEN 30
#define SOSTOK 1
#define EOSTOK 2
#define GRID 148
#define NTHR 512
#define RPB 340            // 148*340 = 50320 >= 50257
#define NCHUNK 8
#define CHUNK 256
#define NUNITS (KB*NCHUNK) // 80
#define SEQW (MAXLEN + 1)  // 31
#define TPB 12
#define NCAND (GRID*KB*TPB)

// ---------------- persistent device state ----------------
__device__ float g_h1[KB*H1D], g_c1[KB*H1D], g_h2[KB*H2D], g_c2[KB*H2D], g_ctx[KB*QQ];
__device__ float g_h1n[KB*H1D], g_c1n[KB*H1D], g_h2n[KB*H2D], g_c2n[KB*H2D], g_ctxn[KB*QQ];
__device__ float g_scores[KB];
__device__ int   g_prev[KB], g_fin[KB], g_seqs[KB*SEQW];
__device__ float g_attM[KB*NCHUNK], g_attA[KB*NCHUNK], g_attB[KB*NCHUNK];
__device__ float g_attC[KB*NCHUNK*QQ];
__device__ double g_sump[GRID*KB];
__device__ float g_cand_val[NCAND];
__device__ int   g_cand_idx[NCAND];
__device__ unsigned g_count = 0;
__device__ unsigned g_epoch = 0;

__device__ __forceinline__ unsigned ordkey(float f){
  unsigned u = __float_as_uint(f);
  return (u & 0x80000000u) ? ~u : (u | 0x80000000u);
}
__device__ __forceinline__ float unordkey(unsigned k){
  unsigned u = (k & 0x80000000u) ? (k & 0x7FFFFFFFu) : ~k;
  return __uint_as_float(u);
}
__device__ __forceinline__ void ffma2(unsigned long long& d, unsigned long long a, unsigned long long b){
  asm("fma.rn.f32x2 %0, %1, %2, %0;" : "+l"(d) : "l"(a), "l"(b));
}
// compensated fp32 FMA accumulate: true value ~= s - c
__device__ __forceinline__ void kfma(float& s, float& c, float a, float b){
  float p  = __fmul_rn(a, b);
  float e  = __fmaf_rn(a, b, -p);
  float y  = p - c;
  float t2 = s + y;
  c = (t2 - s) - y;
  s = t2;
  c -= e;
}

// ---------------- grid barrier with backoff ----------------
__device__ __forceinline__ void gridbar(unsigned& ep){
  __syncthreads();
  if (threadIdx.x==0){
    __threadfence();
    unsigned prev = atomicAdd(&g_count, 1u);
    if (prev == GRID-1u){
      g_count = 0u;
      __threadfence();
      atomicAdd(&g_epoch, 1u);
    } else {
      volatile unsigned* e = &g_epoch;
      while ((int)(*e - ep) < 1) __nanosleep(32);
    }
    __threadfence();
  }
  __syncthreads();
  ep++;
}

// ---------------- shared-memory phase overlays ----------------
struct SM_L1 { float sx[KB*192]; float sh[KB*H1D]; double sg[4*KB]; double snl[4*KB]; };
struct SM_L2 { float sx[KB*H1D]; float sh[KB*H2D]; double sg[4*KB]; double snl[4*KB]; };
struct SM_AT { float h2s[H2D]; float qp[4][QQ]; float qs[QQ]; float ws[CHUNK]; float se[CHUNK];
               float redm[8]; float redab[8][2]; float cs[8][QQ]; };
struct SM_LO { float xs[KB*128]; float lg[KB][RPB]; float wred[16][KB];
               float sM[KB]; float scf[KB][NCHUNK]; double sA[KB]; double sB[KB]; };
struct SM_SE { double sp[256]; unsigned long long skeys[256*10]; unsigned long long wmax[16];
               unsigned long long swin; unsigned long long topk[KB];
               float slse[KB]; float sscore[KB]; float sval[KB];
               int sfin[KB]; int spb[KB]; int stok[KB]; int sseq[KB*SEQW]; };
#define SMRAW_BYTES 25600

__global__ void __launch_bounds__(NTHR) mega_kernel(
  const float* __restrict__ enc_key, const float* __restrict__ enc_val,
  const float* __restrict__ mask,    const float* __restrict__ emb,
  const float* __restrict__ Wih1, const float* __restrict__ Whh1,
  const float* __restrict__ bih1, const float* __restrict__ bhh1,
  const float* __restrict__ Wih2, const float* __restrict__ Whh2,
  const float* __restrict__ bih2, const float* __restrict__ bhh2,
  const float* __restrict__ Wq, const float* __restrict__ bq,
  const float* __restrict__ Wc, const float* __restrict__ bc,
  float* __restrict__ out)
{
  __shared__ __align__(16) char smraw[SMRAW_BYTES];
  __shared__ unsigned s_ep0;
  int t = threadIdx.x, bid = blockIdx.x;
  int lane = t & 31, wid = t >> 5;

  static_assert(sizeof(SM_L1) <= SMRAW_BYTES, "SM_L1 overflow");
  static_assert(sizeof(SM_L2) <= SMRAW_BYTES, "SM_L2 overflow");
  static_assert(sizeof(SM_AT) <= SMRAW_BYTES, "SM_AT overflow");
  static_assert(sizeof(SM_LO) <= SMRAW_BYTES, "SM_LO overflow");
  static_assert(sizeof(SM_SE) <= SMRAW_BYTES, "SM_SE overflow");

  if (t==0){
    volatile unsigned* e = &g_epoch;
    s_ep0 = *e;
  }
  __syncthreads();
  unsigned ep = s_ep0;

  if (bid==0){
    for (int i=t;i<KB*H1D;i+=NTHR){ g_h1[i]=0.f; g_c1[i]=0.f; }
    for (int i=t;i<KB*H2D;i+=NTHR){ g_h2[i]=0.f; g_c2[i]=0.f; }
    for (int i=t;i<KB*QQ;i+=NTHR)  g_ctx[i]=0.f;
    for (int i=t;i<KB*SEQW;i+=NTHR) g_seqs[i]=SOSTOK;
    if (t<KB){ g_scores[t]=0.f; g_prev[t]=SOSTOK; g_fin[t]=0; }
  }
  gridbar(ep);

  for (int step=0; step<MAXLEN; step++){

    // ---------- LSTM1: blocks 0..127, all 16 warps ----------
    if (bid < H1D){
      SM_L1* s1 = (SM_L1*)smraw;
      int n = bid;
      for (int i=t;i<KB*192;i+=NTHR){
        int b=i/192, j=i%192;
        s1->sx[i] = (j<EE) ? emb[(size_t)g_prev[b]*EE + j] : g_ctx[b*QQ + (j-EE)];
      }
      for (int i=t;i<KB*H1D;i+=NTHR) s1->sh[i] = g_h1[i];
      __syncthreads();
      {
        int g = wid>>2, bset = wid&3;   // warp -> (gate, beam subset)
        const float* wi = Wih1 + (size_t)(g*H1D+n)*192;
        const float* wh = Whh1 + (size_t)(g*H1D+n)*H1D;
        double bb = (double)bih1[g*H1D+n] + (double)bhh1[g*H1D+n];
        for (int b=bset; b<KB; b+=4){
          float s=0.f, c=0.f;
          #pragma unroll 2
          for (int j=lane;j<192;j+=32) kfma(s, c, wi[j], s1->sx[b*192+j]);
          #pragma unroll 2
          for (int j=lane;j<H1D;j+=32) kfma(s, c, wh[j], s1->sh[b*H1D+j]);
          for (int o=16;o>0;o>>=1){
            s += __shfl_down_sync(0xffffffffu, s, o);
            c += __shfl_down_sync(0xffffffffu, c, o);
          }
          if (lane==0) s1->sg[g*KB+b] = ((double)s - (double)c) + bb;
        }
      }
      __syncthreads();
      if (t<4*KB){
        int gg=t/KB;
        double v = s1->sg[t];
        s1->snl[t] = (gg==2) ? tanh(v) : 1.0/(1.0+exp(-v));
      }
      __syncthreads();
      if (t<KB){
        double cd = s1->snl[1*KB+t]*(double)g_c1[t*H1D+n] + s1->snl[0*KB+t]*s1->snl[2*KB+t];
        float cf = (float)cd;
        g_c1n[t*H1D+n] = cf;
        g_h1n[t*H1D+n] = (float)(s1->snl[3*KB+t]*tanh((double)cf));
      }
    }
    gridbar(ep);

    // ---------- LSTM2: blocks 0..63, all 16 warps ----------
    if (bid < H2D){
      SM_L2* s2 = (SM_L2*)smraw;
      int n = bid;
      for (int i=t;i<KB*H1D;i+=NTHR) s2->sx[i] = g_h1n[i];
      for (int i=t;i<KB*H2D;i+=NTHR) s2->sh[i] = g_h2[i];
      __syncthreads();
      {
        int g = wid>>2, bset = wid&3;
        const float* wi = Wih2 + (size_t)(g*H2D+n)*H1D;
        const float* wh = Whh2 + (size_t)(g*H2D+n)*H2D;
        double bb = (double)bih2[g*H2D+n] + (double)bhh2[g*H2D+n];
        for (int b=bset; b<KB; b+=4){
          float s=0.f, c=0.f;
          #pragma unroll 2
          for (int j=lane;j<H1D;j+=32) kfma(s, c, wi[j], s2->sx[b*H1D+j]);
          for (int j=lane;j<H2D;j+=32) kfma(s, c, wh[j], s2->sh[b*H2D+j]);
          for (int o=16;o>0;o>>=1){
            s += __shfl_down_sync(0xffffffffu, s, o);
            c += __shfl_down_sync(0xffffffffu, c, o);
          }
          if (lane==0) s2->sg[g*KB+b] = ((double)s - (double)c) + bb;
        }
      }
      __syncthreads();
      if (t<4*KB){
        int gg=t/KB;
        double v = s2->sg[t];
        s2->snl[t] = (gg==2) ? tanh(v) : 1.0/(1.0+exp(-v));
      }
      __syncthreads();
      if (t<KB){
        double cd = s2->snl[1*KB+t]*(double)g_c2[t*H2D+n] + s2->snl[0*KB+t]*s2->snl[2*KB+t];
        float cf = (float)cd;
        g_c2n[t*H2D+n] = cf;
        g_h2n[t*H2D+n] = (float)(s2->snl[3*KB+t]*tanh((double)cf));
      }
    }
    gridbar(ep);

    // ---------- attention: 80 units (beam, 256-token chunk) ----------
    if (bid < NUNITS){
      SM_AT* sa = (SM_AT*)smraw;
      int beam = bid>>3, ch = bid&7;
      if (t<H2D) sa->h2s[t] = g_h2n[beam*H2D+t];
      __syncthreads();
      if (t < 256){
        int qi = t&63, part = t>>6;
        const float* w = Wq + qi*H2D + part*16;
        float s=0.f, c=0.f;
        #pragma unroll
        for (int j=0;j<16;j++) kfma(s, c, w[j], sa->h2s[part*16+j]);
        sa->qp[part][qi] = s - c;
      }
      __syncthreads();
      if (t<QQ) sa->qs[t] = bq[t] + ((sa->qp[0][t]+sa->qp[1][t])+(sa->qp[2][t]+sa->qp[3][t]));
      __syncthreads();
      // energies: 16-lane group per token, coalesced key reads
      {
        int half = lane>>4, l16 = lane&15;
        float4 qv = ((const float4*)sa->qs)[l16];
        #pragma unroll
        for (int it=0; it<8; it++){
          int tl = it*32 + wid*2 + half;          // 0..255
          int tok = ch*CHUNK + tl;
          float4 kv = ((const float4*)(enc_key + (size_t)tok*QQ))[l16];
          float s=0.f, c=0.f;
          kfma(s,c,qv.x,kv.x); kfma(s,c,qv.y,kv.y);
          kfma(s,c,qv.z,kv.z); kfma(s,c,qv.w,kv.w);
          float p = s - c;
          for (int o=8;o>0;o>>=1) p += __shfl_down_sync(0xffffffffu, p, o);
          if (l16==0) sa->se[tl] = p;
        }
      }
      __syncthreads();
      float e = -1e30f;
      if (t < 256) e = sa->se[t];
      float m = e;
      for (int o=16;o>0;o>>=1) m = fmaxf(m, __shfl_down_sync(0xffffffffu, m, o));
      if (lane==0 && wid<8) sa->redm[wid]=m;
      __syncthreads();
      float M = sa->redm[0];
      #pragma unroll
      for (int q=1;q<8;q++) M = fmaxf(M, sa->redm[q]);
      float wexp=0.f, wmask=0.f;
      if (t < 256){
        int tok = ch*CHUNK + t;
        wexp = expf(e-M);
        wmask = wexp*mask[tok];
        sa->ws[t] = wmask;
      }
      float a=wexp, b2=wmask;
      for (int o=16;o>0;o>>=1){
        a  += __shfl_down_sync(0xffffffffu, a, o);
        b2 += __shfl_down_sync(0xffffffffu, b2, o);
      }
      if (lane==0 && wid<8){ sa->redab[wid][0]=a; sa->redab[wid][1]=b2; }
      __syncthreads();
      {
        int v = t&63, grp = t>>6;      // 8 groups x 32 tokens, all 512 threads
        const float* vb = enc_val + (size_t)(ch*CHUNK + grp*32)*QQ + v;
        float s0=0,c0=0,s1=0,c1=0;
        #pragma unroll 4
        for (int tl=0; tl<32; tl+=2){
          kfma(s0,c0, sa->ws[grp*32+tl],   vb[(size_t)tl*QQ]);
          kfma(s1,c1, sa->ws[grp*32+tl+1], vb[(size_t)(tl+1)*QQ]);
        }
        sa->cs[grp][v] = (s0-c0)+(s1-c1);
      }
      __syncthreads();
      if (t<QQ){
        float cc = ((sa->cs[0][t]+sa->cs[1][t])+(sa->cs[2][t]+sa->cs[3][t]))
                 + ((sa->cs[4][t]+sa->cs[5][t])+(sa->cs[6][t]+sa->cs[7][t]));
        g_attC[(beam*NCHUNK+ch)*QQ + t] = cc;
      }
      if (t==0){
        g_attM[beam*NCHUNK+ch]=M;
        g_attA[beam*NCHUNK+ch]=((sa->redab[0][0]+sa->redab[1][0])+(sa->redab[2][0]+sa->redab[3][0]))
                              +((sa->redab[4][0]+sa->redab[5][0])+(sa->redab[6][0]+sa->redab[7][0]));
        g_attB[beam*NCHUNK+ch]=((sa->redab[0][1]+sa->redab[1][1])+(sa->redab[2][1]+sa->redab[3][1]))
                              +((sa->redab[4][1]+sa->redab[5][1])+(sa->redab[6][1]+sa->redab[7][1]));
      }
    }
    gridbar(ep);

    // ---------- logits (+merge prologue): all 148 blocks, 340 threads x 1 row ----------
    {
      SM_LO* so = (SM_LO*)smraw;
      if (t<KB){
        float M=-1e30f;
        #pragma unroll
        for (int c=0;c<NCHUNK;c++) M = fmaxf(M, g_attM[t*NCHUNK+c]);
        so->sM[t]=M;
      }
      __syncthreads();
      if (t<KB*NCHUNK){
        int b=t/NCHUNK;
        so->scf[b][t%NCHUNK] = expf(g_attM[t]-so->sM[b]);
      }
      __syncthreads();
      if (t<KB){
        double A=0.0, B=0.0;
        #pragma unroll
        for (int c=0;c<NCHUNK;c++){
          A += (double)g_attA[t*NCHUNK+c]*(double)so->scf[t][c];
          B += (double)g_attB[t*NCHUNK+c]*(double)so->scf[t][c];
        }
        so->sA[t]=A; so->sB[t]=B;
      }
      __syncthreads();
      for (int i=t;i<KB*128;i+=NTHR){
        int b=i>>7, j=i&127;
        float x;
        if (j < H2D) x = g_h2n[b*H2D+j];
        else {
          int v = j - H2D;
          float s=0.f, c=0.f;
          #pragma unroll
          for (int cc=0;cc<NCHUNK;cc++) kfma(s, c, g_attC[(b*NCHUNK+cc)*QQ+v], so->scf[b][cc]);
          double Cd = (double)s - (double)c;
          x = (float)((Cd/so->sA[b]) / fmax(so->sB[b]/so->sA[b], 2e-30));
          if (bid == 0) g_ctxn[b*QQ+v] = x;
        }
        so->xs[i] = x;
      }
      __syncthreads();
      float ex[KB];
      #pragma unroll
      for (int b=0;b<KB;b++) ex[b]=0.f;
      if (t < RPB){
        int v0 = bid*RPB + t;
        bool ok0 = v0 < VV;
        const ulonglong2* wr0 = (const ulonglong2*)(Wc + (size_t)(ok0?v0:0)*128);
        const ulonglong2* xp = (const ulonglong2*)so->xs;
        unsigned long long a0[KB];
        #pragma unroll
        for (int b=0;b<KB;b++) a0[b]=0ull;
        #pragma unroll 2
        for (int j=0;j<32;j++){
          ulonglong2 w0 = wr0[j];
          #pragma unroll
          for (int b=0;b<KB;b++){
            ulonglong2 xv = xp[b*32+j];
            ffma2(a0[b], w0.x, xv.x);
            ffma2(a0[b], w0.y, xv.y);
          }
        }
        float bc0 = ok0 ? bc[v0] : 0.f;
        #pragma unroll
        for (int b=0;b<KB;b++){
          float lo0 = __uint_as_float((unsigned)(a0[b] & 0xffffffffu));
          float hi0 = __uint_as_float((unsigned)(a0[b] >> 32));
          float l0 = ok0 ? (lo0 + hi0) + bc0 : -1e30f;
          so->lg[b][t] = l0;
          ex[b] = expf(l0);
        }
      }
      #pragma unroll
      for (int b=0;b<KB;b++){
        float s = ex[b];
        for (int o=16;o>0;o>>=1) s += __shfl_down_sync(0xffffffffu, s, o);
        if (lane==0) so->wred[wid][b] = s;
      }
      __syncthreads();
      if (t<KB){
        double s=0.0;
        for (int w=0;w<16;w++) s += (double)so->wred[w][t];
        g_sump[bid*KB+t] = s;
      }
      if (wid < KB){
        int bm = wid;
        for (int j=0;j<TPB;j++){
          unsigned long long best=0ull;
          for (int r2=lane; r2<RPB; r2+=32){
            unsigned long long k = ((unsigned long long)ordkey(so->lg[bm][r2])<<32) | (unsigned)(~(unsigned)r2);
            if (k>best) best=k;
          }
          for (int o=16;o>0;o>>=1){
            unsigned long long ok = __shfl_down_sync(0xffffffffu, best, o);
            if (ok>best) best=ok;
          }
          best = __shfl_sync(0xffffffffu, best, 0);
          int rs = (int)(~(unsigned)(best & 0xffffffffu));
          if (lane==0){
            g_cand_val[(bid*KB+bm)*TPB+j] = so->lg[bm][rs];
            g_cand_idx[(bid*KB+bm)*TPB+j] = bid*RPB + rs;
            so->lg[bm][rs] = -1e30f;
          }
          __syncwarp();
        }
      }
    }
    gridbar(ep);

    // ---------- select: block 0 ----------
    if (bid==0){
      SM_SE* se = (SM_SE*)smraw;
      {
        double s=0.0;
        if (t < 250){
          int b = t/25, part = t%25;
          for (int b2=part; b2<GRID; b2+=25) s += g_sump[b2*KB+b];
        }
        if (t < 256) se->sp[t]=s;
      }
      __syncthreads();
      if (t<KB){
        double s=0.0;
        for (int q=0;q<25;q++) s += se->sp[t*25+q];
        se->slse[t] = (float)log(s);
        se->sscore[t] = g_scores[t];
        se->sfin[t] = g_fin[t];
      }
      __syncthreads();
      if (t < 256){
        unsigned long long list[10];
        #pragma unroll
        for (int j=0;j<10;j++) list[j]=0ull;
        for (int c=t;c<NCAND;c+=256){
          int b = (c/TPB)%KB;
          if (se->sfin[b]) continue;
          if (step==0 && b>0) continue;
          float logp = g_cand_val[c] - se->slse[b];
          float v = se->sscore[b] + logp;
          int flat = b*VV + g_cand_idx[c];
          unsigned long long k = ((unsigned long long)ordkey(v)<<32) | (unsigned)(~(unsigned)flat);
          if (k > list[9]){
            list[9]=k;
            for (int j=8;j>=0;j--){
              if (list[j] < list[j+1]){ unsigned long long tmp=list[j]; list[j]=list[j+1]; list[j+1]=tmp; }
              else break;
            }
          }
        }
        if (t<KB && se->sfin[t]){
          float v = se->sscore[t];
          int flat = t*VV + EOSTOK;
          unsigned long long k = ((unsigned long long)ordkey(v)<<32) | (unsigned)(~(unsigned)flat);
          if (k > list[9]){
            list[9]=k;
            for (int j=8;j>=0;j--){
              if (list[j] < list[j+1]){ unsigned long long tmp=list[j]; list[j]=list[j+1]; list[j+1]=tmp; }
              else break;
            }
          }
        }
        #pragma unroll
        for (int j=0;j<10;j++) se->skeys[t*10+j]=list[j];
      }
      __syncthreads();
      for (int j=0;j<10;j++){
        unsigned long long m=0ull;
        if (t < 256){
          #pragma unroll
          for (int q=0;q<10;q++){ unsigned long long k=se->skeys[t*10+q]; if (k>m) m=k; }
        }
        for (int o=16;o>0;o>>=1){
          unsigned long long ok = __shfl_down_sync(0xffffffffu, m, o);
          if (ok>m) m=ok;
        }
        if (lane==0) se->wmax[wid]=m;
        __syncthreads();
        if (t==0){
          unsigned long long w=se->wmax[0];
          for (int q=1;q<16;q++) if (se->wmax[q]>w) w=se->wmax[q];
          se->swin=w; se->topk[j]=w;
        }
        __syncthreads();
        unsigned long long win = se->swin;
        if (t < 256){
          #pragma unroll
          for (int q=0;q<10;q++) if (se->skeys[t*10+q]==win) se->skeys[t*10+q]=0ull;
        }
        __syncthreads();
      }
      if (t<KB){
        unsigned long long k = se->topk[t];
        se->sval[t] = unordkey((unsigned)(k>>32));
        int flat = (int)(~(unsigned)(k & 0xffffffffu));
        se->spb[t]  = flat / VV;
        se->stok[t] = flat % VV;
      }
      for (int i=t;i<KB*SEQW;i+=NTHR) se->sseq[i] = g_seqs[i];
      __syncthreads();
      for (int i=t;i<KB*H1D;i+=NTHR){
        int nb=i>>7, u=i&127;
        g_h1[i]=g_h1n[se->spb[nb]*H1D+u];
        g_c1[i]=g_c1n[se->spb[nb]*H1D+u];
      }
      for (int i=t;i<KB*H2D;i+=NTHR){
        int nb=i>>6, u=i&63;
        g_h2[i]=g_h2n[se->spb[nb]*H2D+u];
        g_c2[i]=g_c2n[se->spb[nb]*H2D+u];
        g_ctx[i]=g_ctxn[se->spb[nb]*QQ+u];
      }
      for (int i=t;i<KB*SEQW;i+=NTHR){
        int nb=i/SEQW, cc=i%SEQW;
        g_seqs[i] = se->sseq[se->spb[nb]*SEQW+cc];
      }
      __syncthreads();
      if (t<KB){
        g_seqs[t*SEQW + step + 1] = se->stok[t];
        g_prev[t]   = se->stok[t];
        g_scores[t] = se->sval[t];
        g_fin[t]    = se->sfin[se->spb[t]] | (se->stok[t]==EOSTOK);
      }
    }
    gridbar(ep);
  }

  // ---------- finalize: block 0 ----------
  if (bid==0){
    SM_SE* se = (SM_SE*)smraw;
    if (t<KB){
      int first=-1;
      for (int c=1;c<=MAXLEN;c++){
        if (g_seqs[t*SEQW+c]==EOSTOK){ first=c-1; break; }
      }
      float len = (first>=0) ? (float)(first+2) : (float)(MAXLEN+2);
      se->sval[t] = (float)((double)g_scores[t] / pow((double)len, 1.2));
    }
    __syncthreads();
    for (int i=t;i<KB*SEQW;i+=NTHR) out[i] = (float)g_seqs[i];
    if (t<KB){
      out[KB*SEQW + t]       = g_scores[t];
      out[KB*SEQW + KB + t]  = se->sval[t];
    }
  }
}

extern "C" void kernel_launch(void* const* d_in, const int* in_sizes, int n_in,
                              void* d_out, int out_size){
  const float* enc_key = (const float*)d_in[0];
  const float* enc_val = (const float*)d_in[1];
  const float* mask    = (const float*)d_in[2];
  const float* emb     = (const float*)d_in[3];
  const float* Wih1    = (const float*)d_in[4];
  const float* Whh1    = (const float*)d_in[5];
  const float* bih1    = (const float*)d_in[6];
  const float* bhh1    = (const float*)d_in[7];
  const float* Wih2    = (const float*)d_in[8];
  const float* Whh2    = (const float*)d_in[9];
  const float* bih2    = (const float*)d_in[10];
  const float* bhh2    = (const float*)d_in[11];
  const float* Wq      = (const float*)d_in[12];
  const float* bq      = (const float*)d_in[13];
  const float* Wc      = (const float*)d_in[14];
  const float* bc      = (const float*)d_in[15];

  mega_kernel<<<GRID,NTHR>>>(enc_key, enc_val, mask, emb,
                             Wih1, Whh1, bih1, bhh1,
                             Wih2, Whh2, bih2, bhh2,
                             Wq, bq, Wc, bc, (float*)d_out);
}